// round 14
// baseline (speedup 1.0000x reference)
#include <cuda_runtime.h>
#include <cuda_bf16.h>
#include <math.h>

#define NOP     2048
#define NGATES  8192
#define NACT    1024
#define NB      32

#define NBLK    128        // uniform: 16 h-indices per block
#define CNT     16
#define NROWS   64
// dynamic smem layout (bytes)
#define OFF_W     0                               // 64 rows x 2048 B int8
#define OFF_PART  (NROWS * NOP)                   // 131072 (part[4][64] s32)
#define OFF_XG    (OFF_PART + 4 * 64 * 4)         // 132096 (f32[64])
#define OFF_FS    (OFF_XG + 64 * 4)               // 132352 (f32[64])
// padded so 2 CTAs can NEVER co-reside on one SM (barrier needs all resident)
#define SMEM_TOTAL (160 * 1024)

// ---------------- scratch (static device globals) ---------------------------
__device__ __align__(16) signed char g_w8[(size_t)NGATES * NOP];  // 16 MB int8
__device__ __align__(16) float g_wsc[NGATES];     // per-row scale rowmax/127^2
__device__ __align__(16) float g_xg[NGATES];
__device__ __align__(16) signed char g_h8[2][NOP];  // h exchange, int8 (x127)
__device__ __align__(16) float g_hall[(size_t)NACT * NOP];
__device__ __align__(16) float g_ent[NACT];
__device__ __align__(16) float g_rein[NACT];
// 8 replicated monotonic arrival counters on separate 128B lines.
// Arrive = 8x red.release (fire-and-forget, parallel). Wait = ONE poller per
// block on replica (b&7) -> 16 spinners/line. Reset by detect_act.
__device__ __align__(128) unsigned g_cntR[8 * 32];
__device__ int g_act64 = 0;

// ---------------- helpers ---------------------------------------------------
__device__ __forceinline__ float tanh_fast(float x) {
    float y;
    asm("tanh.approx.f32 %0, %1;" : "=f"(y) : "f"(x));
    return y;
}
__device__ __forceinline__ float sigmoid_fast(float x) {
    return 0.5f * tanh_fast(0.5f * x) + 0.5f;
}

__device__ __forceinline__ void bar_arrive_all() {
#pragma unroll
    for (int i = 0; i < 8; i++)
        asm volatile("red.release.gpu.global.add.u32 [%0], %1;"
                     :: "l"(&g_cntR[i * 32]), "r"(1u) : "memory");
}
__device__ __forceinline__ unsigned ld_acquire(const unsigned* p) {
    unsigned v;
    asm volatile("ld.acquire.gpu.global.u32 %0, [%1];" : "=r"(v) : "l"(p) : "memory");
    return v;
}

// quarter-row dot: 512 K-values int8 x int8, exact s32 accumulate via dp4a
__device__ __forceinline__ int dotq8(uint4 w, uint4 h) {
    int a = __dp4a((int)w.x, (int)h.x, 0);
    int b = __dp4a((int)w.y, (int)h.y, 0);
    a = __dp4a((int)w.z, (int)h.z, a);
    b = __dp4a((int)w.w, (int)h.w, b);
    return a + b;
}

// ---------------- action dtype detect + counter reset ------------------------
__global__ void detect_act(const int* __restrict__ act_words) {
    __shared__ int any;
    if (threadIdx.x == 0) any = 0;
    g_cntR[threadIdx.x] = 0;   // 256 threads cover all replica words
    __syncthreads();
    for (int i = 1 + 2 * threadIdx.x; i < 512; i += 2 * blockDim.x)
        if (act_words[i] != 0) atomicOr(&any, 1);
    __syncthreads();
    if (threadIdx.x == 0) g_act64 = (any == 0) ? 1 : 0;
}

// ---------------- prep: W_hh fp32 -> int8 with per-row scale ------------------
__global__ void prep_w8(const float* __restrict__ Whh) {
    int warp = (blockIdx.x * blockDim.x + threadIdx.x) >> 5;   // row 0..8191
    int lane = threadIdx.x & 31;
    if (warp >= NGATES) return;
    const float4* rp = reinterpret_cast<const float4*>(Whh + (size_t)warp * NOP);
    float4 v[16];
    float mx = 0.f;
#pragma unroll
    for (int i = 0; i < 16; i++) {
        v[i] = rp[lane + 32 * i];
        mx = fmaxf(mx, fmaxf(fmaxf(fabsf(v[i].x), fabsf(v[i].y)),
                             fmaxf(fabsf(v[i].z), fabsf(v[i].w))));
    }
#pragma unroll
    for (int o = 16; o; o >>= 1) mx = fmaxf(mx, __shfl_xor_sync(0xffffffffu, mx, o));
    const float inv = 127.f / fmaxf(mx, 1e-30f);
    unsigned* dst = reinterpret_cast<unsigned*>(g_w8 + (size_t)warp * NOP);
#pragma unroll
    for (int i = 0; i < 16; i++) {
        int a = __float2int_rn(v[i].x * inv) & 255;
        int b = __float2int_rn(v[i].y * inv) & 255;
        int c = __float2int_rn(v[i].z * inv) & 255;
        int d = __float2int_rn(v[i].w * inv) & 255;
        dst[lane + 32 * i] = (unsigned)(a | (b << 8) | (c << 16) | (d << 24));
    }
    if (lane == 0) g_wsc[warp] = mx * (1.f / (127.f * 127.f));
}

// ---------------- prep: x_gates ----------------------------------------------
__global__ void prep_xg(const float* __restrict__ Wih,
                        const float* __restrict__ bih,
                        const float* __restrict__ bhh) {
    int warp = (blockIdx.x * blockDim.x + threadIdx.x) >> 5;
    int lane = threadIdx.x & 31;
    if (warp >= NGATES) return;
    const float4* rp = reinterpret_cast<const float4*>(Wih + (size_t)warp * NOP);
    float s = 0.f;
    for (int m = lane; m < NOP / 4; m += 32) {
        float4 v = rp[m];
        s += (v.x + v.y) + (v.z + v.w);
    }
#pragma unroll
    for (int o = 16; o; o >>= 1) s += __shfl_xor_sync(0xffffffffu, s, o);
    if (lane == 0) g_xg[warp] = s * (1.0f / NOP) + bih[warp] + bhh[warp];
}

// ---------------- main persistent LSTM kernel -------------------------------
__global__ void __launch_bounds__(1024, 1) lstm_main() {
    extern __shared__ unsigned char smem[];
    signed char* w_s = reinterpret_cast<signed char*>(smem + OFF_W);
    int*   part = reinterpret_cast<int*>(smem + OFF_PART);    // [4][64] s32
    float* xg_s = reinterpret_cast<float*>(smem + OFF_XG);    // [64]
    float* fs_s = reinterpret_cast<float*>(smem + OFF_FS);    // [64] row scales

    const int tid  = threadIdx.x;
    const int lane = tid & 31;
    const int wid  = tid >> 5;           // 0..31
    const int qtr  = wid >> 3;           // K-quarter 0..3
    const int ww   = wid & 7;            // warp within quarter

    const int b    = blockIdx.x;         // 0..127
    const int base = b * CNT;

    // this block's poll replica
    const unsigned* my_cnt = &g_cntR[(b & 7) * 32];

    // ---- stage int8 weight slice into smem (2 KB per row) ----
    for (int l = wid; l < NROWS; l += 32) {
        int j = (l >> 4) * NOP + base + (l & 15);
        const uint4* src = reinterpret_cast<const uint4*>(g_w8 + (size_t)j * NOP);
        uint4* dst = reinterpret_cast<uint4*>(w_s + (size_t)l * NOP);
        for (int m = lane; m < 128; m += 32) dst[m] = src[m];
    }
    if (tid < NROWS) {
        int j = (tid >> 4) * NOP + base + (tid & 15);
        xg_s[tid] = g_xg[j];
        fs_s[tid] = g_wsc[j];
    }

    // ---- publish h(0) = 0 (int8), arrive ----
    float c_reg = 0.f, h_reg = 0.f;     // warp0, lane < CNT
    if (wid == 0) {
        if (lane < CNT) {
            short z = 0;
            asm volatile("st.global.cg.u8 [%0], %1;"
                         :: "l"(&g_h8[0][base + lane]), "h"(z) : "memory");
        }
        __syncwarp();
        if (lane == 0) bar_arrive_all();
    }

    int cur = 0;

    for (int t = 0; t < NACT; ++t) {
        // previous step's output store hides in the wait window
        if (wid == 0 && lane < CNT && t > 0)
            g_hall[(size_t)(t - 1) * NOP + base + lane] = h_reg;

        // ---- wait: ONE poller per block on its replica, then syncthreads ----
        if (tid == 0) {
            const unsigned tgt = (unsigned)NBLK * (unsigned)(t + 1);
            while (ld_acquire(my_cnt) < tgt) { }
        }
        __syncthreads();   // acquire -> CTA-wide happens-before

        // ---- load this warp's int8 h chunk (16 values/lane) from L2 ----
        const uint4* hp = reinterpret_cast<const uint4*>(&g_h8[cur][0]);
        uint4 hq = __ldcg(hp + (qtr * 32 + lane));

        // ---- 8 uniform rows per warp (quarter-dots, exact s32) ----
        int s[8];
        const uint4* wb = reinterpret_cast<const uint4*>(w_s) + qtr * 32 + lane;
#pragma unroll
        for (int i = 0; i < 8; i++)
            s[i] = dotq8(wb[(size_t)(ww + 8 * i) * 128], hq);

        // interleaved cross-lane reduction: 8 parallel shfl chains (s32)
#pragma unroll
        for (int o = 16; o; o >>= 1) {
#pragma unroll
            for (int i = 0; i < 8; i++)
                s[i] += __shfl_xor_sync(0xffffffffu, s[i], o);
        }
        if (lane == 0) {
#pragma unroll
            for (int i = 0; i < 8; i++)
                part[qtr * 64 + ww + 8 * i] = s[i];
        }
        __syncthreads();

        // ---- cell update (warp 0), publish int8 h(t+1), arrive ----
        if (wid == 0) {
            if (lane < CNT) {
                float gv[4];
#pragma unroll
                for (int g = 0; g < 4; ++g) {
                    int l = g * CNT + lane;
                    int acc = (part[l] + part[64 + l])
                            + (part[128 + l] + part[192 + l]);
                    gv[g] = (float)acc * fs_s[l] + xg_s[l];
                }
                float ii = sigmoid_fast(gv[0]);
                float ff = sigmoid_fast(gv[1]);
                float gg = tanh_fast(gv[2]);
                float oo = sigmoid_fast(gv[3]);
                c_reg = ff * c_reg + ii * gg;
                h_reg = oo * tanh_fast(c_reg);
                if (t + 1 < NACT) {
                    short hq8 = (short)__float2int_rn(h_reg * 127.f);
                    asm volatile("st.global.cg.u8 [%0], %1;"
                                 :: "l"(&g_h8[cur ^ 1][base + lane]), "h"(hq8)
                                 : "memory");
                }
            }
            __syncwarp();
            if (lane == 0 && t + 1 < NACT) bar_arrive_all();
        }
        cur ^= 1;
    }

    // final output row
    if (wid == 0 && lane < CNT)
        g_hall[(size_t)(NACT - 1) * NOP + base + lane] = h_reg;
}

// ---------------- epilogue ----------------------------------------------------
__global__ void post_rows(const int* __restrict__ act_words,
                          const float* __restrict__ rewards) {
    __shared__ float row[NOP];
    __shared__ float red[256];
    const int t = blockIdx.x, tid = threadIdx.x;
    const float* src = g_hall + (size_t)t * NOP;
    for (int i = tid; i < NOP; i += 256) row[i] = src[i];
    __syncthreads();

    float m = -1e30f;
    for (int i = tid; i < NOP; i += 256) m = fmaxf(m, row[i]);
    red[tid] = m; __syncthreads();
    for (int s = 128; s; s >>= 1) {
        if (tid < s) red[tid] = fmaxf(red[tid], red[tid + s]);
        __syncthreads();
    }
    m = red[0]; __syncthreads();

    float se = 0.f, sx = 0.f;
    for (int i = tid; i < NOP; i += 256) {
        float x = row[i];
        float e = expf(x - m);
        se += e; sx += e * x;
    }
    red[tid] = se; __syncthreads();
    for (int s = 128; s; s >>= 1) {
        if (tid < s) red[tid] += red[tid + s];
        __syncthreads();
    }
    const float SE = red[0]; __syncthreads();
    red[tid] = sx; __syncthreads();
    for (int s = 128; s; s >>= 1) {
        if (tid < s) red[tid] += red[tid + s];
        __syncthreads();
    }
    const float SX = red[0]; __syncthreads();

    const float lse = m + logf(SE);
    if (tid == 0) g_ent[t] = lse - SX / SE;

    if (tid < 32) {
        int flat = tid * NACT + t;
        int a = g_act64 ? act_words[2 * flat] : act_words[flat];
        a = a < 0 ? 0 : (a >= NOP ? NOP - 1 : a);
        float lp = row[a] - lse;
        float pr = rewards[tid] * lp;
#pragma unroll
        for (int o = 16; o; o >>= 1) pr += __shfl_xor_sync(0xffffffffu, pr, o);
        if (tid == 0) g_rein[t] = pr;
    }
}

__global__ void post_final(float* __restrict__ out) {
    __shared__ float r1[256], r2[256];
    const int tid = threadIdx.x;
    float se = 0.f, sr = 0.f;
    for (int i = tid; i < NACT; i += 256) { se += g_ent[i]; sr += g_rein[i]; }
    r1[tid] = se; r2[tid] = sr; __syncthreads();
    for (int s = 128; s; s >>= 1) {
        if (tid < s) { r1[tid] += r1[tid + s]; r2[tid] += r2[tid + s]; }
        __syncthreads();
    }
    if (tid == 0) out[0] = (-r2[0] + (float)NB * r1[0]) / (float)NB;
}

// ---------------- launch -------------------------------------------------------
extern "C" void kernel_launch(void* const* d_in, const int* in_sizes, int n_in,
                              void* d_out, int out_size) {
    const float* Wih     = (const float*)d_in[0];
    const float* Whh     = (const float*)d_in[1];
    const float* bih     = (const float*)d_in[2];
    const float* bhh     = (const float*)d_in[3];
    const float* rewards = (const float*)d_in[4];
    const int*   actw    = (const int*)d_in[5];
    float* out = (float*)d_out;

    // 128 blocks <= SM count (147+) and 160 KB smem forces 1 CTA/SM:
    // all blocks resident -> the counter barrier cannot deadlock.
    cudaFuncSetAttribute(lstm_main, cudaFuncAttributeMaxDynamicSharedMemorySize,
                         SMEM_TOTAL);

    detect_act<<<1, 256>>>(actw);
    prep_w8<<<1024, 256>>>(Whh);
    prep_xg<<<1024, 256>>>(Wih, bih, bhh);
    lstm_main<<<NBLK, 1024, SMEM_TOTAL>>>();
    post_rows<<<NACT, 256>>>(actw, rewards);
    post_final<<<1, 256>>>(out);
}

// round 15
// speedup vs baseline: 2.1529x; 2.1529x over previous
#include <cuda_runtime.h>
#include <cuda_bf16.h>
#include <math.h>

#define NOP     2048
#define NGATES  8192
#define NACT    1024
#define NB      32

#define MAXROWS 56
// dynamic smem layout (bytes)
#define OFF_W     0                               // 56 rows x 2048 B int8
#define OFF_PART  (MAXROWS * NOP)                 // 114688 (part[4][64] s32)
#define OFF_XG    (OFF_PART + 4 * 64 * 4)         // 115712 (f32[64])
#define OFF_FS    (OFF_XG + 64 * 4)               // 115968 (f32[64])
// padded so 2 CTAs can NEVER co-reside on one SM (barrier needs 1 CTA/SM)
#define SMEM_TOTAL (160 * 1024)

// ---------------- scratch (static device globals) ---------------------------
__device__ __align__(16) signed char g_w8[(size_t)NGATES * NOP];  // 16 MB int8
__device__ __align__(16) float g_wsc[NGATES];     // per-row scale rowmax/127^2
__device__ __align__(16) float g_xg[NGATES];
__device__ __align__(16) signed char g_h8[2][NOP];  // h exchange, int8 (x127)
__device__ __align__(16) float g_hall[(size_t)NACT * NOP];
__device__ __align__(16) float g_ent[NACT];
__device__ __align__(16) float g_rein[NACT];
// single monotonic arrival counter (R13-proven optimum). Arrive = red.release;
// wait = ONE poller per block + __syncthreads. Reset by detect_act.
__device__ unsigned g_cnt = 0;
__device__ int g_act64 = 0;

// ---------------- helpers ---------------------------------------------------
__device__ __forceinline__ float tanh_fast(float x) {
    float y;
    asm("tanh.approx.f32 %0, %1;" : "=f"(y) : "f"(x));
    return y;
}
__device__ __forceinline__ float sigmoid_fast(float x) {
    return 0.5f * tanh_fast(0.5f * x) + 0.5f;
}

__device__ __forceinline__ void bar_arrive_red() {
    asm volatile("red.release.gpu.global.add.u32 [%0], %1;"
                 :: "l"(&g_cnt), "r"(1u) : "memory");
}
__device__ __forceinline__ unsigned ld_acquire(const unsigned* p) {
    unsigned v;
    asm volatile("ld.acquire.gpu.global.u32 %0, [%1];" : "=r"(v) : "l"(p) : "memory");
    return v;
}

// 2-deep pipelined wait: keep two acquires in flight so the sampling period
// is ~RT/2 instead of RT. Traffic only 2x (304 loads/RT on the line, well
// under the ~600 contention threshold calibrated in R11/R14).
__device__ __forceinline__ void bar_wait_pipelined(unsigned tgt) {
    unsigned a = ld_acquire(&g_cnt);
    if (a >= tgt) return;
    unsigned b = ld_acquire(&g_cnt);
    for (;;) {
        if (a >= tgt) return;
        a = b;
        b = ld_acquire(&g_cnt);
    }
}

// quarter-row dot: 512 K-values int8 x int8, exact s32 accumulate via dp4a
__device__ __forceinline__ int dotq8(uint4 w, uint4 h) {
    int a = __dp4a((int)w.x, (int)h.x, 0);
    int b = __dp4a((int)w.y, (int)h.y, 0);
    a = __dp4a((int)w.z, (int)h.z, a);
    b = __dp4a((int)w.w, (int)h.w, b);
    return a + b;
}

// ---------------- action dtype detect + counter reset ------------------------
__global__ void detect_act(const int* __restrict__ act_words) {
    __shared__ int any;
    if (threadIdx.x == 0) { any = 0; g_cnt = 0; }
    __syncthreads();
    for (int i = 1 + 2 * threadIdx.x; i < 512; i += 2 * blockDim.x)
        if (act_words[i] != 0) atomicOr(&any, 1);
    __syncthreads();
    if (threadIdx.x == 0) g_act64 = (any == 0) ? 1 : 0;
}

// ---------------- prep: W_hh fp32 -> int8 with per-row scale ------------------
__global__ void prep_w8(const float* __restrict__ Whh) {
    int warp = (blockIdx.x * blockDim.x + threadIdx.x) >> 5;   // row 0..8191
    int lane = threadIdx.x & 31;
    if (warp >= NGATES) return;
    const float4* rp = reinterpret_cast<const float4*>(Whh + (size_t)warp * NOP);
    float4 v[16];
    float mx = 0.f;
#pragma unroll
    for (int i = 0; i < 16; i++) {
        v[i] = rp[lane + 32 * i];
        mx = fmaxf(mx, fmaxf(fmaxf(fabsf(v[i].x), fabsf(v[i].y)),
                             fmaxf(fabsf(v[i].z), fabsf(v[i].w))));
    }
#pragma unroll
    for (int o = 16; o; o >>= 1) mx = fmaxf(mx, __shfl_xor_sync(0xffffffffu, mx, o));
    const float inv = 127.f / fmaxf(mx, 1e-30f);
    unsigned* dst = reinterpret_cast<unsigned*>(g_w8 + (size_t)warp * NOP);
#pragma unroll
    for (int i = 0; i < 16; i++) {
        int a = __float2int_rn(v[i].x * inv) & 255;
        int b = __float2int_rn(v[i].y * inv) & 255;
        int c = __float2int_rn(v[i].z * inv) & 255;
        int d = __float2int_rn(v[i].w * inv) & 255;
        dst[lane + 32 * i] = (unsigned)(a | (b << 8) | (c << 16) | (d << 24));
    }
    if (lane == 0) g_wsc[warp] = mx * (1.f / (127.f * 127.f));
}

// ---------------- prep: x_gates ----------------------------------------------
__global__ void prep_xg(const float* __restrict__ Wih,
                        const float* __restrict__ bih,
                        const float* __restrict__ bhh) {
    int warp = (blockIdx.x * blockDim.x + threadIdx.x) >> 5;
    int lane = threadIdx.x & 31;
    if (warp >= NGATES) return;
    const float4* rp = reinterpret_cast<const float4*>(Wih + (size_t)warp * NOP);
    float s = 0.f;
    for (int m = lane; m < NOP / 4; m += 32) {
        float4 v = rp[m];
        s += (v.x + v.y) + (v.z + v.w);
    }
#pragma unroll
    for (int o = 16; o; o >>= 1) s += __shfl_xor_sync(0xffffffffu, s, o);
    if (lane == 0) g_xg[warp] = s * (1.0f / NOP) + bih[warp] + bhh[warp];
}

// ---------------- main persistent LSTM kernel -------------------------------
__global__ void __launch_bounds__(1024, 1) lstm_main() {
    extern __shared__ unsigned char smem[];
    signed char* w_s = reinterpret_cast<signed char*>(smem + OFF_W);
    int*   part = reinterpret_cast<int*>(smem + OFF_PART);    // [4][64] s32
    float* xg_s = reinterpret_cast<float*>(smem + OFF_XG);    // [64]
    float* fs_s = reinterpret_cast<float*>(smem + OFF_FS);    // [64] row scales

    const int tid  = threadIdx.x;
    const int lane = tid & 31;
    const int wid  = tid >> 5;           // 0..31
    const int qtr  = wid >> 3;           // K-quarter 0..3
    const int ww   = wid & 7;            // warp within quarter

    const int nblk = gridDim.x;
    const int b    = blockIdx.x;
    const int q    = NOP / nblk, r = NOP % nblk;
    const int base = b * q + (b < r ? b : r);
    const int cnt  = q + (b < r ? 1 : 0);          // <= 14 for >=147 blocks
    const int nrows = 4 * cnt;                      // <= 56, all in smem

    // ---- stage int8 weight slice into smem (2 KB per row) ----
    for (int l = wid; l < nrows; l += 32) {
        int j = (l / cnt) * NOP + base + (l % cnt);
        const uint4* src = reinterpret_cast<const uint4*>(g_w8 + (size_t)j * NOP);
        uint4* dst = reinterpret_cast<uint4*>(w_s + (size_t)l * NOP);
        for (int m = lane; m < 128; m += 32) dst[m] = src[m];
    }
    for (int l = tid; l < nrows; l += blockDim.x) {
        int j = (l / cnt) * NOP + base + (l % cnt);
        xg_s[l] = g_xg[j];
        fs_s[l] = g_wsc[j];
    }

    // ---- publish h(0) = 0 (int8), arrive ----
    float c_reg = 0.f, h_reg = 0.f;     // warp0, lane < cnt
    if (wid == 0) {
        if (lane < cnt) {
            short z = 0;
            asm volatile("st.global.cg.u8 [%0], %1;"
                         :: "l"(&g_h8[0][base + lane]), "h"(z) : "memory");
        }
        __syncwarp();
        if (lane == 0) bar_arrive_red();
    }

    int cur = 0;

    for (int t = 0; t < NACT; ++t) {
        // previous step's output store hides in the wait window
        if (wid == 0 && lane < cnt && t > 0)
            g_hall[(size_t)(t - 1) * NOP + base + lane] = h_reg;

        // ---- wait: ONE poller per block (2-deep pipelined), syncthreads ----
        if (tid == 0)
            bar_wait_pipelined((unsigned)nblk * (unsigned)(t + 1));
        __syncthreads();   // acquire -> CTA-wide happens-before

        // ---- load this warp's int8 h chunk (16 values/lane) from L2 ----
        const uint4* hp = reinterpret_cast<const uint4*>(&g_h8[cur][0]);
        uint4 hq = __ldcg(hp + (qtr * 32 + lane));

        // ---- 6 uniform rows + 1 guarded tail row (quarter-dots, s32) ----
        int s[7];
        const uint4* wb = reinterpret_cast<const uint4*>(w_s) + qtr * 32 + lane;
#pragma unroll
        for (int i = 0; i < 6; i++)
            s[i] = dotq8(wb[(size_t)(ww + 8 * i) * 128], hq);
        {
            int l6 = 48 + ww;
            s[6] = (l6 < nrows) ? dotq8(wb[(size_t)l6 * 128], hq) : 0;
        }

        // interleaved cross-lane reduction: 7 parallel shfl chains (s32)
#pragma unroll
        for (int o = 16; o; o >>= 1) {
#pragma unroll
            for (int i = 0; i < 7; i++)
                s[i] += __shfl_xor_sync(0xffffffffu, s[i], o);
        }
        if (lane == 0) {
#pragma unroll
            for (int i = 0; i < 7; i++) {
                int l = ww + 8 * i;
                if (l < nrows) part[qtr * 64 + l] = s[i];
            }
        }
        __syncthreads();

        // ---- cell update (warp 0), publish int8 h(t+1), arrive ----
        if (wid == 0) {
            if (lane < cnt) {
                float gv[4];
#pragma unroll
                for (int g = 0; g < 4; ++g) {
                    int l = g * cnt + lane;
                    int acc = (part[l] + part[64 + l])
                            + (part[128 + l] + part[192 + l]);
                    gv[g] = (float)acc * fs_s[l] + xg_s[l];
                }
                float ii = sigmoid_fast(gv[0]);
                float ff = sigmoid_fast(gv[1]);
                float gg = tanh_fast(gv[2]);
                float oo = sigmoid_fast(gv[3]);
                c_reg = ff * c_reg + ii * gg;
                h_reg = oo * tanh_fast(c_reg);
                if (t + 1 < NACT) {
                    short hq8 = (short)__float2int_rn(h_reg * 127.f);
                    asm volatile("st.global.cg.u8 [%0], %1;"
                                 :: "l"(&g_h8[cur ^ 1][base + lane]), "h"(hq8)
                                 : "memory");
                }
            }
            __syncwarp();
            if (lane == 0 && t + 1 < NACT) bar_arrive_red();
        }
        cur ^= 1;
    }

    // final output row
    if (wid == 0 && lane < cnt)
        g_hall[(size_t)(NACT - 1) * NOP + base + lane] = h_reg;
}

// ---------------- epilogue ----------------------------------------------------
__global__ void post_rows(const int* __restrict__ act_words,
                          const float* __restrict__ rewards) {
    __shared__ float row[NOP];
    __shared__ float red[256];
    const int t = blockIdx.x, tid = threadIdx.x;
    const float* src = g_hall + (size_t)t * NOP;
    for (int i = tid; i < NOP; i += 256) row[i] = src[i];
    __syncthreads();

    float m = -1e30f;
    for (int i = tid; i < NOP; i += 256) m = fmaxf(m, row[i]);
    red[tid] = m; __syncthreads();
    for (int s = 128; s; s >>= 1) {
        if (tid < s) red[tid] = fmaxf(red[tid], red[tid + s]);
        __syncthreads();
    }
    m = red[0]; __syncthreads();

    float se = 0.f, sx = 0.f;
    for (int i = tid; i < NOP; i += 256) {
        float x = row[i];
        float e = expf(x - m);
        se += e; sx += e * x;
    }
    red[tid] = se; __syncthreads();
    for (int s = 128; s; s >>= 1) {
        if (tid < s) red[tid] += red[tid + s];
        __syncthreads();
    }
    const float SE = red[0]; __syncthreads();
    red[tid] = sx; __syncthreads();
    for (int s = 128; s; s >>= 1) {
        if (tid < s) red[tid] += red[tid + s];
        __syncthreads();
    }
    const float SX = red[0]; __syncthreads();

    const float lse = m + logf(SE);
    if (tid == 0) g_ent[t] = lse - SX / SE;

    if (tid < 32) {
        int flat = tid * NACT + t;
        int a = g_act64 ? act_words[2 * flat] : act_words[flat];
        a = a < 0 ? 0 : (a >= NOP ? NOP - 1 : a);
        float lp = row[a] - lse;
        float pr = rewards[tid] * lp;
#pragma unroll
        for (int o = 16; o; o >>= 1) pr += __shfl_xor_sync(0xffffffffu, pr, o);
        if (tid == 0) g_rein[t] = pr;
    }
}

__global__ void post_final(float* __restrict__ out) {
    __shared__ float r1[256], r2[256];
    const int tid = threadIdx.x;
    float se = 0.f, sr = 0.f;
    for (int i = tid; i < NACT; i += 256) { se += g_ent[i]; sr += g_rein[i]; }
    r1[tid] = se; r2[tid] = sr; __syncthreads();
    for (int s = 128; s; s >>= 1) {
        if (tid < s) { r1[tid] += r1[tid + s]; r2[tid] += r2[tid + s]; }
        __syncthreads();
    }
    if (tid == 0) out[0] = (-r2[0] + (float)NB * r1[0]) / (float)NB;
}

// ---------------- launch -------------------------------------------------------
extern "C" void kernel_launch(void* const* d_in, const int* in_sizes, int n_in,
                              void* d_out, int out_size) {
    const float* Wih     = (const float*)d_in[0];
    const float* Whh     = (const float*)d_in[1];
    const float* bih     = (const float*)d_in[2];
    const float* bhh     = (const float*)d_in[3];
    const float* rewards = (const float*)d_in[4];
    const int*   actw    = (const int*)d_in[5];
    float* out = (float*)d_out;

    int dev = 0;
    cudaGetDevice(&dev);
    int sms = 148;
    cudaDeviceGetAttribute(&sms, cudaDevAttrMultiProcessorCount, dev);
    if (sms < 147) sms = 148;   // need cnt <= 14 (56 rows fit smem)
    cudaFuncSetAttribute(lstm_main, cudaFuncAttributeMaxDynamicSharedMemorySize,
                         SMEM_TOTAL);

    detect_act<<<1, 256>>>(actw);
    prep_w8<<<1024, 256>>>(Whh);
    prep_xg<<<1024, 256>>>(Wih, bih, bhh);
    lstm_main<<<sms, 1024, SMEM_TOTAL>>>();
    post_rows<<<NACT, 256>>>(actw, rewards);
    post_final<<<1, 256>>>(out);
}

// round 16
// speedup vs baseline: 2.2408x; 1.0408x over previous
#include <cuda_runtime.h>
#include <cuda_bf16.h>
#include <math.h>

#define NOP     2048
#define NGATES  8192
#define NACT    1024
#define NB      32

#define MAXROWS 56
// dynamic smem layout (bytes)
#define OFF_W     0                               // 56 rows x 2048 B int8
#define OFF_PART  (MAXROWS * NOP)                 // 114688 (part[4][64] s32)
#define OFF_XG    (OFF_PART + 4 * 64 * 4)         // 115712 (f32[64])
#define OFF_FS    (OFF_XG + 64 * 4)               // 115968 (f32[64])
// padded so 2 CTAs can NEVER co-reside on one SM (barrier needs 1 CTA/SM)
#define SMEM_TOTAL (160 * 1024)

// ---------------- scratch (static device globals) ---------------------------
__device__ __align__(16) signed char g_w8[(size_t)NGATES * NOP];  // 16 MB int8
__device__ __align__(16) float g_wsc[NGATES];     // per-row scale rowmax/127^2
__device__ __align__(16) float g_xg[NGATES];
__device__ __align__(16) signed char g_h8[2][NOP];  // h exchange, int8 (x127)
__device__ __align__(16) float g_hall[(size_t)NACT * NOP];
__device__ __align__(16) float g_ent[NACT];
__device__ __align__(16) float g_rein[NACT];
// single monotonic arrival counter (R13-proven optimum). Arrive =
// atom.acq_rel.add returning old (last arriver learns it may skip the poll);
// wait = ONE poller per block + __syncthreads. Reset by detect_act.
__device__ unsigned g_cnt = 0;
__device__ int g_act64 = 0;

// ---------------- helpers ---------------------------------------------------
__device__ __forceinline__ float tanh_fast(float x) {
    float y;
    asm("tanh.approx.f32 %0, %1;" : "=f"(y) : "f"(x));
    return y;
}
__device__ __forceinline__ float sigmoid_fast(float x) {
    return 0.5f * tanh_fast(0.5f * x) + 0.5f;
}

// arrival with return: acq_rel orders our h stores (release) and, for the
// last arriver, acquires all other blocks' release-arrivals.
__device__ __forceinline__ unsigned bar_arrive_atom() {
    unsigned old;
    asm volatile("atom.acq_rel.gpu.global.add.u32 %0, [%1], %2;"
                 : "=r"(old) : "l"(&g_cnt), "r"(1u) : "memory");
    return old;
}
__device__ __forceinline__ unsigned ld_acquire(const unsigned* p) {
    unsigned v;
    asm volatile("ld.acquire.gpu.global.u32 %0, [%1];" : "=r"(v) : "l"(p) : "memory");
    return v;
}

// quarter-row dot: 512 K-values int8 x int8, exact s32 accumulate via dp4a
__device__ __forceinline__ int dotq8(uint4 w, uint4 h) {
    int a = __dp4a((int)w.x, (int)h.x, 0);
    int b = __dp4a((int)w.y, (int)h.y, 0);
    a = __dp4a((int)w.z, (int)h.z, a);
    b = __dp4a((int)w.w, (int)h.w, b);
    return a + b;
}

// ---------------- action dtype detect + counter reset ------------------------
__global__ void detect_act(const int* __restrict__ act_words) {
    __shared__ int any;
    if (threadIdx.x == 0) { any = 0; g_cnt = 0; }
    __syncthreads();
    for (int i = 1 + 2 * threadIdx.x; i < 512; i += 2 * blockDim.x)
        if (act_words[i] != 0) atomicOr(&any, 1);
    __syncthreads();
    if (threadIdx.x == 0) g_act64 = (any == 0) ? 1 : 0;
}

// ---------------- prep: W_hh fp32 -> int8 with per-row scale ------------------
__global__ void prep_w8(const float* __restrict__ Whh) {
    int warp = (blockIdx.x * blockDim.x + threadIdx.x) >> 5;   // row 0..8191
    int lane = threadIdx.x & 31;
    if (warp >= NGATES) return;
    const float4* rp = reinterpret_cast<const float4*>(Whh + (size_t)warp * NOP);
    float4 v[16];
    float mx = 0.f;
#pragma unroll
    for (int i = 0; i < 16; i++) {
        v[i] = rp[lane + 32 * i];
        mx = fmaxf(mx, fmaxf(fmaxf(fabsf(v[i].x), fabsf(v[i].y)),
                             fmaxf(fabsf(v[i].z), fabsf(v[i].w))));
    }
#pragma unroll
    for (int o = 16; o; o >>= 1) mx = fmaxf(mx, __shfl_xor_sync(0xffffffffu, mx, o));
    const float inv = 127.f / fmaxf(mx, 1e-30f);
    unsigned* dst = reinterpret_cast<unsigned*>(g_w8 + (size_t)warp * NOP);
#pragma unroll
    for (int i = 0; i < 16; i++) {
        int a = __float2int_rn(v[i].x * inv) & 255;
        int b = __float2int_rn(v[i].y * inv) & 255;
        int c = __float2int_rn(v[i].z * inv) & 255;
        int d = __float2int_rn(v[i].w * inv) & 255;
        dst[lane + 32 * i] = (unsigned)(a | (b << 8) | (c << 16) | (d << 24));
    }
    if (lane == 0) g_wsc[warp] = mx * (1.f / (127.f * 127.f));
}

// ---------------- prep: x_gates ----------------------------------------------
__global__ void prep_xg(const float* __restrict__ Wih,
                        const float* __restrict__ bih,
                        const float* __restrict__ bhh) {
    int warp = (blockIdx.x * blockDim.x + threadIdx.x) >> 5;
    int lane = threadIdx.x & 31;
    if (warp >= NGATES) return;
    const float4* rp = reinterpret_cast<const float4*>(Wih + (size_t)warp * NOP);
    float s = 0.f;
    for (int m = lane; m < NOP / 4; m += 32) {
        float4 v = rp[m];
        s += (v.x + v.y) + (v.z + v.w);
    }
#pragma unroll
    for (int o = 16; o; o >>= 1) s += __shfl_xor_sync(0xffffffffu, s, o);
    if (lane == 0) g_xg[warp] = s * (1.0f / NOP) + bih[warp] + bhh[warp];
}

// ---------------- main persistent LSTM kernel -------------------------------
__global__ void __launch_bounds__(1024, 1) lstm_main() {
    extern __shared__ unsigned char smem[];
    signed char* w_s = reinterpret_cast<signed char*>(smem + OFF_W);
    int*   part = reinterpret_cast<int*>(smem + OFF_PART);    // [4][64] s32
    float* xg_s = reinterpret_cast<float*>(smem + OFF_XG);    // [64]
    float* fs_s = reinterpret_cast<float*>(smem + OFF_FS);    // [64] row scales

    const int tid  = threadIdx.x;
    const int lane = tid & 31;
    const int wid  = tid >> 5;           // 0..31
    const int qtr  = wid >> 3;           // K-quarter 0..3
    const int ww   = wid & 7;            // warp within quarter

    const int nblk = gridDim.x;
    const int b    = blockIdx.x;
    const int q    = NOP / nblk, r = NOP % nblk;
    const int base = b * q + (b < r ? b : r);
    const int cnt  = q + (b < r ? 1 : 0);          // <= 14 for >=147 blocks
    const int nrows = 4 * cnt;                      // <= 56, all in smem

    // ---- stage int8 weight slice into smem (2 KB per row) ----
    for (int l = wid; l < nrows; l += 32) {
        int j = (l / cnt) * NOP + base + (l % cnt);
        const uint4* src = reinterpret_cast<const uint4*>(g_w8 + (size_t)j * NOP);
        uint4* dst = reinterpret_cast<uint4*>(w_s + (size_t)l * NOP);
        for (int m = lane; m < 128; m += 32) dst[m] = src[m];
    }
    for (int l = tid; l < nrows; l += blockDim.x) {
        int j = (l / cnt) * NOP + base + (l % cnt);
        xg_s[l] = g_xg[j];
        fs_s[l] = g_wsc[j];
    }

    // tid0-local: did our own arrival complete the barrier we're about to wait on?
    unsigned skip = 0;

    // ---- publish h(0) = 0 (int8), arrive ----
    float c_reg = 0.f, h_reg = 0.f;     // warp0, lane < cnt
    if (wid == 0) {
        if (lane < cnt) {
            short z = 0;
            asm volatile("st.global.cg.u8 [%0], %1;"
                         :: "l"(&g_h8[0][base + lane]), "h"(z) : "memory");
        }
        __syncwarp();
        if (lane == 0) {
            unsigned old = bar_arrive_atom();
            skip = (old == (unsigned)nblk - 1u) ? 1u : 0u;
        }
    }

    int cur = 0;

    for (int t = 0; t < NACT; ++t) {
        // previous step's output store hides in the wait window
        if (wid == 0 && lane < cnt && t > 0)
            g_hall[(size_t)(t - 1) * NOP + base + lane] = h_reg;

        // ---- wait: ONE poller per block (skipped if we closed the barrier) --
        if (tid == 0) {
            if (!skip) {
                const unsigned tgt = (unsigned)nblk * (unsigned)(t + 1);
                while (ld_acquire(&g_cnt) < tgt) { }
            }
            skip = 0;
        }
        __syncthreads();   // acquire(/acq_rel) -> CTA-wide happens-before

        // ---- load this warp's int8 h chunk (16 values/lane) from L2 ----
        const uint4* hp = reinterpret_cast<const uint4*>(&g_h8[cur][0]);
        uint4 hq = __ldcg(hp + (qtr * 32 + lane));

        // ---- 6 uniform rows + 1 guarded tail row (quarter-dots, s32) ----
        int s[7];
        const uint4* wb = reinterpret_cast<const uint4*>(w_s) + qtr * 32 + lane;
#pragma unroll
        for (int i = 0; i < 6; i++)
            s[i] = dotq8(wb[(size_t)(ww + 8 * i) * 128], hq);
        {
            int l6 = 48 + ww;
            s[6] = (l6 < nrows) ? dotq8(wb[(size_t)l6 * 128], hq) : 0;
        }

        // interleaved cross-lane reduction: 7 parallel shfl chains (s32)
#pragma unroll
        for (int o = 16; o; o >>= 1) {
#pragma unroll
            for (int i = 0; i < 7; i++)
                s[i] += __shfl_xor_sync(0xffffffffu, s[i], o);
        }
        if (lane == 0) {
#pragma unroll
            for (int i = 0; i < 7; i++) {
                int l = ww + 8 * i;
                if (l < nrows) part[qtr * 64 + l] = s[i];
            }
        }
        __syncthreads();

        // ---- cell update (warp 0), publish int8 h(t+1), arrive ----
        if (wid == 0) {
            if (lane < cnt) {
                float gv[4];
#pragma unroll
                for (int g = 0; g < 4; ++g) {
                    int l = g * cnt + lane;
                    int acc = (part[l] + part[64 + l])
                            + (part[128 + l] + part[192 + l]);
                    gv[g] = (float)acc * fs_s[l] + xg_s[l];
                }
                float ii = sigmoid_fast(gv[0]);
                float ff = sigmoid_fast(gv[1]);
                float gg = tanh_fast(gv[2]);
                float oo = sigmoid_fast(gv[3]);
                c_reg = ff * c_reg + ii * gg;
                h_reg = oo * tanh_fast(c_reg);
                if (t + 1 < NACT) {
                    short hq8 = (short)__float2int_rn(h_reg * 127.f);
                    asm volatile("st.global.cg.u8 [%0], %1;"
                                 :: "l"(&g_h8[cur ^ 1][base + lane]), "h"(hq8)
                                 : "memory");
                }
            }
            __syncwarp();
            if (lane == 0 && t + 1 < NACT) {
                unsigned old = bar_arrive_atom();
                skip = (old == (unsigned)nblk * (unsigned)(t + 2) - 1u) ? 1u : 0u;
            }
        }
        cur ^= 1;
    }

    // final output row
    if (wid == 0 && lane < cnt)
        g_hall[(size_t)(NACT - 1) * NOP + base + lane] = h_reg;
}

// ---------------- epilogue ----------------------------------------------------
__global__ void post_rows(const int* __restrict__ act_words,
                          const float* __restrict__ rewards) {
    __shared__ float row[NOP];
    __shared__ float red[256];
    const int t = blockIdx.x, tid = threadIdx.x;
    const float* src = g_hall + (size_t)t * NOP;
    for (int i = tid; i < NOP; i += 256) row[i] = src[i];
    __syncthreads();

    float m = -1e30f;
    for (int i = tid; i < NOP; i += 256) m = fmaxf(m, row[i]);
    red[tid] = m; __syncthreads();
    for (int s = 128; s; s >>= 1) {
        if (tid < s) red[tid] = fmaxf(red[tid], red[tid + s]);
        __syncthreads();
    }
    m = red[0]; __syncthreads();

    float se = 0.f, sx = 0.f;
    for (int i = tid; i < NOP; i += 256) {
        float x = row[i];
        float e = expf(x - m);
        se += e; sx += e * x;
    }
    red[tid] = se; __syncthreads();
    for (int s = 128; s; s >>= 1) {
        if (tid < s) red[tid] += red[tid + s];
        __syncthreads();
    }
    const float SE = red[0]; __syncthreads();
    red[tid] = sx; __syncthreads();
    for (int s = 128; s; s >>= 1) {
        if (tid < s) red[tid] += red[tid + s];
        __syncthreads();
    }
    const float SX = red[0]; __syncthreads();

    const float lse = m + logf(SE);
    if (tid == 0) g_ent[t] = lse - SX / SE;

    if (tid < 32) {
        int flat = tid * NACT + t;
        int a = g_act64 ? act_words[2 * flat] : act_words[flat];
        a = a < 0 ? 0 : (a >= NOP ? NOP - 1 : a);
        float lp = row[a] - lse;
        float pr = rewards[tid] * lp;
#pragma unroll
        for (int o = 16; o; o >>= 1) pr += __shfl_xor_sync(0xffffffffu, pr, o);
        if (tid == 0) g_rein[t] = pr;
    }
}

__global__ void post_final(float* __restrict__ out) {
    __shared__ float r1[256], r2[256];
    const int tid = threadIdx.x;
    float se = 0.f, sr = 0.f;
    for (int i = tid; i < NACT; i += 256) { se += g_ent[i]; sr += g_rein[i]; }
    r1[tid] = se; r2[tid] = sr; __syncthreads();
    for (int s = 128; s; s >>= 1) {
        if (tid < s) { r1[tid] += r1[tid + s]; r2[tid] += r2[tid + s]; }
        __syncthreads();
    }
    if (tid == 0) out[0] = (-r2[0] + (float)NB * r1[0]) / (float)NB;
}

// ---------------- launch -------------------------------------------------------
extern "C" void kernel_launch(void* const* d_in, const int* in_sizes, int n_in,
                              void* d_out, int out_size) {
    const float* Wih     = (const float*)d_in[0];
    const float* Whh     = (const float*)d_in[1];
    const float* bih     = (const float*)d_in[2];
    const float* bhh     = (const float*)d_in[3];
    const float* rewards = (const float*)d_in[4];
    const int*   actw    = (const int*)d_in[5];
    float* out = (float*)d_out;

    int dev = 0;
    cudaGetDevice(&dev);
    int sms = 148;
    cudaDeviceGetAttribute(&sms, cudaDevAttrMultiProcessorCount, dev);
    if (sms < 147) sms = 148;   // need cnt <= 14 (56 rows fit smem)
    cudaFuncSetAttribute(lstm_main, cudaFuncAttributeMaxDynamicSharedMemorySize,
                         SMEM_TOTAL);

    detect_act<<<1, 256>>>(actw);
    prep_w8<<<1024, 256>>>(Whh);
    prep_xg<<<1024, 256>>>(Wih, bih, bhh);
    lstm_main<<<sms, 1024, SMEM_TOTAL>>>();
    post_rows<<<NACT, 256>>>(actw, rewards);
    post_final<<<1, 256>>>(out);
}

// round 17
// speedup vs baseline: 2.6517x; 1.1834x over previous
#include <cuda_runtime.h>
#include <cuda_bf16.h>
#include <math.h>

#define NOP     2048
#define NGATES  8192
#define NACT    1024
#define NB      32

#define MAXROWS 56
// dynamic smem layout (bytes)
#define OFF_W     0                               // 56 rows x 2048 B int8
#define OFF_PART  (MAXROWS * NOP)                 // 114688 (part[4][64] s32)
#define OFF_XG    (OFF_PART + 4 * 64 * 4)         // 115712 (f32[64])
#define OFF_FS    (OFF_XG + 64 * 4)               // 115968 (f32[64])
// padded so 2 CTAs can NEVER co-reside on one SM (barrier needs 1 CTA/SM)
#define SMEM_TOTAL (160 * 1024)

// ---------------- scratch (static device globals) ---------------------------
__device__ __align__(16) signed char g_w8[(size_t)NGATES * NOP];  // 16 MB int8
__device__ __align__(16) float g_wsc[NGATES];     // per-row scale rowmax/127^2
__device__ __align__(16) float g_xg[NGATES];
__device__ __align__(16) signed char g_h8[2][NOP];  // h exchange, int8 (x127)
__device__ __align__(16) float g_hall[(size_t)NACT * NOP];
__device__ __align__(16) float g_ent[NACT];
__device__ __align__(16) float g_rein[NACT];
// single monotonic arrival counter (R13/R16-proven optimum). Arrive =
// atom.acq_rel.add returning old (last arriver skips the poll);
// wait = ONE poller per block + __syncthreads. Reset by detect_act.
__device__ unsigned g_cnt = 0;
__device__ int g_act64 = 0;

// ---------------- helpers ---------------------------------------------------
__device__ __forceinline__ float tanh_fast(float x) {
    float y;
    asm("tanh.approx.f32 %0, %1;" : "=f"(y) : "f"(x));
    return y;
}
__device__ __forceinline__ float sigmoid_fast(float x) {
    return 0.5f * tanh_fast(0.5f * x) + 0.5f;
}

// arrival with return: acq_rel orders our h stores (release) and, for the
// last arriver, acquires all other blocks' release-arrivals.
__device__ __forceinline__ unsigned bar_arrive_atom() {
    unsigned old;
    asm volatile("atom.acq_rel.gpu.global.add.u32 %0, [%1], %2;"
                 : "=r"(old) : "l"(&g_cnt), "r"(1u) : "memory");
    return old;
}
__device__ __forceinline__ unsigned ld_acquire(const unsigned* p) {
    unsigned v;
    asm volatile("ld.acquire.gpu.global.u32 %0, [%1];" : "=r"(v) : "l"(p) : "memory");
    return v;
}

// quarter-row dot: 512 K-values int8 x int8, exact s32 accumulate via dp4a
__device__ __forceinline__ int dotq8(uint4 w, uint4 h) {
    int a = __dp4a((int)w.x, (int)h.x, 0);
    int b = __dp4a((int)w.y, (int)h.y, 0);
    a = __dp4a((int)w.z, (int)h.z, a);
    b = __dp4a((int)w.w, (int)h.w, b);
    return a + b;
}

// ---------------- action dtype detect + counter reset ------------------------
__global__ void detect_act(const int* __restrict__ act_words) {
    __shared__ int any;
    if (threadIdx.x == 0) { any = 0; g_cnt = 0; }
    __syncthreads();
    for (int i = 1 + 2 * threadIdx.x; i < 512; i += 2 * blockDim.x)
        if (act_words[i] != 0) atomicOr(&any, 1);
    __syncthreads();
    if (threadIdx.x == 0) g_act64 = (any == 0) ? 1 : 0;
}

// ---------------- prep: W_hh fp32 -> int8 with per-row scale ------------------
__global__ void prep_w8(const float* __restrict__ Whh) {
    int warp = (blockIdx.x * blockDim.x + threadIdx.x) >> 5;   // row 0..8191
    int lane = threadIdx.x & 31;
    if (warp >= NGATES) return;
    const float4* rp = reinterpret_cast<const float4*>(Whh + (size_t)warp * NOP);
    float4 v[16];
    float mx = 0.f;
#pragma unroll
    for (int i = 0; i < 16; i++) {
        v[i] = rp[lane + 32 * i];
        mx = fmaxf(mx, fmaxf(fmaxf(fabsf(v[i].x), fabsf(v[i].y)),
                             fmaxf(fabsf(v[i].z), fabsf(v[i].w))));
    }
#pragma unroll
    for (int o = 16; o; o >>= 1) mx = fmaxf(mx, __shfl_xor_sync(0xffffffffu, mx, o));
    const float inv = 127.f / fmaxf(mx, 1e-30f);
    unsigned* dst = reinterpret_cast<unsigned*>(g_w8 + (size_t)warp * NOP);
#pragma unroll
    for (int i = 0; i < 16; i++) {
        int a = __float2int_rn(v[i].x * inv) & 255;
        int b = __float2int_rn(v[i].y * inv) & 255;
        int c = __float2int_rn(v[i].z * inv) & 255;
        int d = __float2int_rn(v[i].w * inv) & 255;
        dst[lane + 32 * i] = (unsigned)(a | (b << 8) | (c << 16) | (d << 24));
    }
    if (lane == 0) g_wsc[warp] = mx * (1.f / (127.f * 127.f));
}

// ---------------- prep: x_gates ----------------------------------------------
__global__ void prep_xg(const float* __restrict__ Wih,
                        const float* __restrict__ bih,
                        const float* __restrict__ bhh) {
    int warp = (blockIdx.x * blockDim.x + threadIdx.x) >> 5;
    int lane = threadIdx.x & 31;
    if (warp >= NGATES) return;
    const float4* rp = reinterpret_cast<const float4*>(Wih + (size_t)warp * NOP);
    float s = 0.f;
    for (int m = lane; m < NOP / 4; m += 32) {
        float4 v = rp[m];
        s += (v.x + v.y) + (v.z + v.w);
    }
#pragma unroll
    for (int o = 16; o; o >>= 1) s += __shfl_xor_sync(0xffffffffu, s, o);
    if (lane == 0) g_xg[warp] = s * (1.0f / NOP) + bih[warp] + bhh[warp];
}

// ---------------- main persistent LSTM kernel -------------------------------
__global__ void __launch_bounds__(1024, 1) lstm_main() {
    extern __shared__ unsigned char smem[];
    signed char* w_s = reinterpret_cast<signed char*>(smem + OFF_W);
    int*   part = reinterpret_cast<int*>(smem + OFF_PART);    // [4][64] s32
    float* xg_s = reinterpret_cast<float*>(smem + OFF_XG);    // [64]
    float* fs_s = reinterpret_cast<float*>(smem + OFF_FS);    // [64] row scales

    const int tid  = threadIdx.x;
    const int lane = tid & 31;
    const int wid  = tid >> 5;           // 0..31
    const int qtr  = wid >> 3;           // K-quarter 0..3
    const int ww   = wid & 7;            // warp within quarter

    const int nblk = gridDim.x;
    const int b    = blockIdx.x;
    const int q    = NOP / nblk, r = NOP % nblk;
    const int base = b * q + (b < r ? b : r);
    const int cnt  = q + (b < r ? 1 : 0);          // <= 14 for >=147 blocks
    const int nrows = 4 * cnt;                      // <= 56, all in smem

    // ---- stage int8 weight slice into smem (2 KB per row) ----
    for (int l = wid; l < nrows; l += 32) {
        int j = (l / cnt) * NOP + base + (l % cnt);
        const uint4* src = reinterpret_cast<const uint4*>(g_w8 + (size_t)j * NOP);
        uint4* dst = reinterpret_cast<uint4*>(w_s + (size_t)l * NOP);
        for (int m = lane; m < 128; m += 32) dst[m] = src[m];
    }
    for (int l = tid; l < nrows; l += blockDim.x) {
        int j = (l / cnt) * NOP + base + (l % cnt);
        xg_s[l] = g_xg[j];
        fs_s[l] = g_wsc[j];
    }

    // tid0-local: did our own arrival complete the barrier we're about to wait on?
    unsigned skip = 0;

    // ---- publish h(0) = 0 (int8), arrive ----
    float c_reg = 0.f, h_reg = 0.f;     // warp0, lane < cnt
    if (wid == 0) {
        if (lane < cnt) {
            short z = 0;
            asm volatile("st.global.cg.u8 [%0], %1;"
                         :: "l"(&g_h8[0][base + lane]), "h"(z) : "memory");
        }
        __syncwarp();
        if (lane == 0) {
            unsigned old = bar_arrive_atom();
            skip = (old == (unsigned)nblk - 1u) ? 1u : 0u;
        }
    }

    int cur = 0;

    for (int t = 0; t < NACT; ++t) {
        // previous step's output store hides in the wait window
        if (wid == 0 && lane < cnt && t > 0)
            g_hall[(size_t)(t - 1) * NOP + base + lane] = h_reg;

        // ---- wait: ONE poller per block (skipped if we closed the barrier) --
        if (tid == 0) {
            if (!skip) {
                const unsigned tgt = (unsigned)nblk * (unsigned)(t + 1);
                while (ld_acquire(&g_cnt) < tgt) { }
            }
            skip = 0;
        }
        __syncthreads();   // acquire(/acq_rel) -> CTA-wide happens-before

        // ---- load this warp's int8 h chunk (16 values/lane) from L2 ----
        const uint4* hp = reinterpret_cast<const uint4*>(&g_h8[cur][0]);
        uint4 hq = __ldcg(hp + (qtr * 32 + lane));

        // ---- 6 uniform rows + 1 guarded tail row (quarter-dots, s32) ----
        int s[7];
        const uint4* wb = reinterpret_cast<const uint4*>(w_s) + qtr * 32 + lane;
#pragma unroll
        for (int i = 0; i < 6; i++)
            s[i] = dotq8(wb[(size_t)(ww + 8 * i) * 128], hq);
        {
            int l6 = 48 + ww;
            s[6] = (l6 < nrows) ? dotq8(wb[(size_t)l6 * 128], hq) : 0;
        }

        // single-instruction warp reductions (redux.sync.add.s32, exact)
#pragma unroll
        for (int i = 0; i < 7; i++)
            s[i] = __reduce_add_sync(0xffffffffu, s[i]);
        if (lane == 0) {
#pragma unroll
            for (int i = 0; i < 7; i++) {
                int l = ww + 8 * i;
                if (l < nrows) part[qtr * 64 + l] = s[i];
            }
        }
        __syncthreads();

        // ---- cell update (warp 0), publish int8 h(t+1), arrive ----
        if (wid == 0) {
            if (lane < cnt) {
                float gv[4];
#pragma unroll
                for (int g = 0; g < 4; ++g) {
                    int l = g * cnt + lane;
                    int acc = (part[l] + part[64 + l])
                            + (part[128 + l] + part[192 + l]);
                    gv[g] = (float)acc * fs_s[l] + xg_s[l];
                }
                float ii = sigmoid_fast(gv[0]);
                float ff = sigmoid_fast(gv[1]);
                float gg = tanh_fast(gv[2]);
                float oo = sigmoid_fast(gv[3]);
                c_reg = ff * c_reg + ii * gg;
                h_reg = oo * tanh_fast(c_reg);
                if (t + 1 < NACT) {
                    short hq8 = (short)__float2int_rn(h_reg * 127.f);
                    asm volatile("st.global.cg.u8 [%0], %1;"
                                 :: "l"(&g_h8[cur ^ 1][base + lane]), "h"(hq8)
                                 : "memory");
                }
            }
            __syncwarp();
            if (lane == 0 && t + 1 < NACT) {
                unsigned old = bar_arrive_atom();
                skip = (old == (unsigned)nblk * (unsigned)(t + 2) - 1u) ? 1u : 0u;
            }
        }
        cur ^= 1;
    }

    // final output row
    if (wid == 0 && lane < cnt)
        g_hall[(size_t)(NACT - 1) * NOP + base + lane] = h_reg;
}

// ---------------- epilogue ----------------------------------------------------
__global__ void post_rows(const int* __restrict__ act_words,
                          const float* __restrict__ rewards) {
    __shared__ float row[NOP];
    __shared__ float red[256];
    const int t = blockIdx.x, tid = threadIdx.x;
    const float* src = g_hall + (size_t)t * NOP;
    for (int i = tid; i < NOP; i += 256) row[i] = src[i];
    __syncthreads();

    float m = -1e30f;
    for (int i = tid; i < NOP; i += 256) m = fmaxf(m, row[i]);
    red[tid] = m; __syncthreads();
    for (int s = 128; s; s >>= 1) {
        if (tid < s) red[tid] = fmaxf(red[tid], red[tid + s]);
        __syncthreads();
    }
    m = red[0]; __syncthreads();

    float se = 0.f, sx = 0.f;
    for (int i = tid; i < NOP; i += 256) {
        float x = row[i];
        float e = expf(x - m);
        se += e; sx += e * x;
    }
    red[tid] = se; __syncthreads();
    for (int s = 128; s; s >>= 1) {
        if (tid < s) red[tid] += red[tid + s];
        __syncthreads();
    }
    const float SE = red[0]; __syncthreads();
    red[tid] = sx; __syncthreads();
    for (int s = 128; s; s >>= 1) {
        if (tid < s) red[tid] += red[tid + s];
        __syncthreads();
    }
    const float SX = red[0]; __syncthreads();

    const float lse = m + logf(SE);
    if (tid == 0) g_ent[t] = lse - SX / SE;

    if (tid < 32) {
        int flat = tid * NACT + t;
        int a = g_act64 ? act_words[2 * flat] : act_words[flat];
        a = a < 0 ? 0 : (a >= NOP ? NOP - 1 : a);
        float lp = row[a] - lse;
        float pr = rewards[tid] * lp;
#pragma unroll
        for (int o = 16; o; o >>= 1) pr += __shfl_xor_sync(0xffffffffu, pr, o);
        if (tid == 0) g_rein[t] = pr;
    }
}

__global__ void post_final(float* __restrict__ out) {
    __shared__ float r1[256], r2[256];
    const int tid = threadIdx.x;
    float se = 0.f, sr = 0.f;
    for (int i = tid; i < NACT; i += 256) { se += g_ent[i]; sr += g_rein[i]; }
    r1[tid] = se; r2[tid] = sr; __syncthreads();
    for (int s = 128; s; s >>= 1) {
        if (tid < s) { r1[tid] += r1[tid + s]; r2[tid] += r2[tid + s]; }
        __syncthreads();
    }
    if (tid == 0) out[0] = (-r2[0] + (float)NB * r1[0]) / (float)NB;
}

// ---------------- launch -------------------------------------------------------
extern "C" void kernel_launch(void* const* d_in, const int* in_sizes, int n_in,
                              void* d_out, int out_size) {
    const float* Wih     = (const float*)d_in[0];
    const float* Whh     = (const float*)d_in[1];
    const float* bih     = (const float*)d_in[2];
    const float* bhh     = (const float*)d_in[3];
    const float* rewards = (const float*)d_in[4];
    const int*   actw    = (const int*)d_in[5];
    float* out = (float*)d_out;

    int dev = 0;
    cudaGetDevice(&dev);
    int sms = 148;
    cudaDeviceGetAttribute(&sms, cudaDevAttrMultiProcessorCount, dev);
    if (sms < 147) sms = 148;   // need cnt <= 14 (56 rows fit smem)
    cudaFuncSetAttribute(lstm_main, cudaFuncAttributeMaxDynamicSharedMemorySize,
                         SMEM_TOTAL);

    detect_act<<<1, 256>>>(actw);
    prep_w8<<<1024, 256>>>(Whh);
    prep_xg<<<1024, 256>>>(Wih, bih, bhh);
    lstm_main<<<sms, 1024, SMEM_TOTAL>>>();
    post_rows<<<NACT, 256>>>(actw, rewards);
    post_final<<<1, 256>>>(out);
}